// round 8
// baseline (speedup 1.0000x reference)
#include <cuda_runtime.h>
#include <cuda_bf16.h>
#include <math.h>
#include <stdint.h>

// ---------------------------------------------------------------------------
// GRU LM: T=128, B=64, E=H=512, V=10000, 2 layers.
// Round 8: (1) flag-based grid barrier (no atomic serialization),
//          (2) 3-stage GEMM pipeline with 1 syncthreads per chunk.
// ---------------------------------------------------------------------------

#define TT   128
#define BB   64
#define HH   512
#define VV   10000
#define MALL (TT * BB)   // 8192
#define GK   512

#define NBLK   128
#define NTHR   256
#define STRIDE 516

// fp32 scratch
__device__ float g_emb [MALL * HH];
__device__ float g_gx  [MALL * 3 * HH];
__device__ float g_inp [MALL * HH];
__device__ float g_hall[MALL * HH];
__device__ float g_hcur[BB * HH];
__device__ float g_z   [BB * HH];
__device__ float g_rh  [BB * HH];
__device__ float g_wxT [2 * 3 * HH * HH];

// bf16 hi/lo planes
__device__ __nv_bfloat16 g_ahi [MALL * GK];
__device__ __nv_bfloat16 g_alo [MALL * GK];
__device__ __nv_bfloat16 g_wxh [2 * 3 * HH * HH];
__device__ __nv_bfloat16 g_wxl [2 * 3 * HH * HH];
__device__ __nv_bfloat16 g_fch [2 * HH * HH];
__device__ __nv_bfloat16 g_fcl [2 * HH * HH];
__device__ __nv_bfloat16 g_dech[VV * HH];
__device__ __nv_bfloat16 g_decl[VV * HH];

// flag-based grid barrier state (reset by k_reset before each k_recur)
__device__ unsigned g_flags[NBLK];

// ---------------------------------------------------------------------------
__global__ void k_reset() {
    if (threadIdx.x < NBLK) g_flags[threadIdx.x] = 0u;
}

__global__ void k_gather(const int* __restrict__ inp, const float* __restrict__ tbl) {
    int i   = blockIdx.x;
    int row = inp[i];
    const float4* src = reinterpret_cast<const float4*>(tbl + (size_t)row * HH);
    float4*       dst = reinterpret_cast<float4*>(g_emb + (size_t)i * HH);
    for (int j = threadIdx.x; j < HH / 4; j += blockDim.x) dst[j] = src[j];
}

// Transpose W[K][N] -> WT[N][K]
__global__ void k_transpose(const float* __restrict__ W, float* __restrict__ WT,
                            int K, int N) {
    __shared__ float tile[32][33];
    int k0 = blockIdx.y * 32, n0 = blockIdx.x * 32;
    int tx = threadIdx.x, ty = threadIdx.y;
#pragma unroll
    for (int i = 0; i < 32; i += 8)
        if (k0 + ty + i < K && n0 + tx < N)
            tile[ty + i][tx] = W[(size_t)(k0 + ty + i) * N + n0 + tx];
    __syncthreads();
#pragma unroll
    for (int i = 0; i < 32; i += 8)
        if (n0 + ty + i < N && k0 + tx < K)
            WT[(size_t)(n0 + ty + i) * K + k0 + tx] = tile[tx][ty + i];
}

// fp32 -> (hi, lo) bf16 planes. n4 = element count / 4.
__global__ void k_cvt(const float* __restrict__ src,
                      __nv_bfloat16* __restrict__ hi,
                      __nv_bfloat16* __restrict__ lo, int n4) {
    int i = blockIdx.x * blockDim.x + threadIdx.x;
    if (i >= n4) return;
    float4 v = reinterpret_cast<const float4*>(src)[i];
    __nv_bfloat16 h0 = __float2bfloat16(v.x), h1 = __float2bfloat16(v.y),
                  h2 = __float2bfloat16(v.z), h3 = __float2bfloat16(v.w);
    __nv_bfloat16 l0 = __float2bfloat16(v.x - __bfloat162float(h0));
    __nv_bfloat16 l1 = __float2bfloat16(v.y - __bfloat162float(h1));
    __nv_bfloat16 l2 = __float2bfloat16(v.z - __bfloat162float(h2));
    __nv_bfloat16 l3 = __float2bfloat16(v.w - __bfloat162float(h3));
    uint2 hv, lv;
    hv.x = (uint32_t)__bfloat16_as_ushort(h0) | ((uint32_t)__bfloat16_as_ushort(h1) << 16);
    hv.y = (uint32_t)__bfloat16_as_ushort(h2) | ((uint32_t)__bfloat16_as_ushort(h3) << 16);
    lv.x = (uint32_t)__bfloat16_as_ushort(l0) | ((uint32_t)__bfloat16_as_ushort(l1) << 16);
    lv.y = (uint32_t)__bfloat16_as_ushort(l2) | ((uint32_t)__bfloat16_as_ushort(l3) << 16);
    reinterpret_cast<uint2*>(hi)[i] = hv;
    reinterpret_cast<uint2*>(lo)[i] = lv;
}

// ---------------------------------------------------------------------------
// mma.sync helpers
// ---------------------------------------------------------------------------
__device__ __forceinline__ void cpasync16(void* dst_smem, const void* src) {
    uint32_t d = (uint32_t)__cvta_generic_to_shared(dst_smem);
    asm volatile("cp.async.cg.shared.global [%0], [%1], 16;" :: "r"(d), "l"(src));
}
__device__ __forceinline__ void cpasync16z(void* dst_smem, const void* src, int sz) {
    uint32_t d = (uint32_t)__cvta_generic_to_shared(dst_smem);
    asm volatile("cp.async.cg.shared.global [%0], [%1], 16, %2;"
                 :: "r"(d), "l"(src), "r"(sz));
}
__device__ __forceinline__ void cp_commit() { asm volatile("cp.async.commit_group;"); }

__device__ __forceinline__ void ldmx4(uint32_t* r, uint32_t addr) {
    asm volatile("ldmatrix.sync.aligned.m8n8.x4.shared.b16 {%0,%1,%2,%3}, [%4];"
                 : "=r"(r[0]), "=r"(r[1]), "=r"(r[2]), "=r"(r[3]) : "r"(addr));
}
__device__ __forceinline__ void mma16816(float* d, const uint32_t* a, const uint32_t* b) {
    asm volatile(
        "mma.sync.aligned.m16n8k16.row.col.f32.bf16.bf16.f32 "
        "{%0,%1,%2,%3}, {%4,%5,%6,%7}, {%8,%9}, {%0,%1,%2,%3};"
        : "+f"(d[0]), "+f"(d[1]), "+f"(d[2]), "+f"(d[3])
        : "r"(a[0]), "r"(a[1]), "r"(a[2]), "r"(a[3]), "r"(b[0]), "r"(b[1]));
}

// ---------------------------------------------------------------------------
// Tensor-core GEMM: C[M,N] = A[M,512] @ B[N,512]^T + bias (fp32 via bf16x3).
// CTA 128x128, BK=32, 256 threads, 3-stage cp.async pipeline, 1 sync/chunk.
// ---------------------------------------------------------------------------
#define NCH 48   // 3 phases * 512/32

__global__ __launch_bounds__(256)
void k_gemm_tc(const __nv_bfloat16* __restrict__ Ahi,
               const __nv_bfloat16* __restrict__ Alo,
               const __nv_bfloat16* __restrict__ Bhi,
               const __nv_bfloat16* __restrict__ Blo,
               const float* __restrict__ bias, float* __restrict__ C, int N) {
    __shared__ __align__(16) char smem[3 * 16384];  // 3 stages: A 8KB + B 8KB

    const int tid  = threadIdx.x;
    const int lane = tid & 31;
    const int wid  = tid >> 5;
    const int wm   = wid >> 2;
    const int wn   = wid & 3;
    const int m0   = blockIdx.y * 128;
    const int n0   = blockIdx.x * 128;

    const int sRow0 = tid >> 2;
    const int sC16  = tid & 3;
    const int sSw0  = sC16 ^ ((sRow0 >> 1) & 3);
    const int sRow1 = sRow0 + 64;
    const int sSw1  = sC16 ^ ((sRow1 >> 1) & 3);

    const int aRow16 = lane & 15;
    const int aKhalf = lane >> 4;
    const int bL8 = lane & 7, bG = lane >> 3;

    int  aRowOff[4], aXor[4];
#pragma unroll
    for (int mt = 0; mt < 4; mt++) {
        int r = wm * 64 + mt * 16 + aRow16;
        aRowOff[mt] = r * 64;
        aXor[mt]    = (r >> 1) & 3;
    }
    int  bRowOff[2], bXor[2];
#pragma unroll
    for (int p = 0; p < 2; p++) {
        int r = wn * 32 + p * 16 + ((bG >> 1) << 3) + bL8;
        bRowOff[p] = r * 64;
        bXor[p]    = (r >> 1) & 3;
    }
    const uint32_t smemBase = (uint32_t)__cvta_generic_to_shared(smem);

    float acc[4][4][4];
#pragma unroll
    for (int i = 0; i < 4; i++)
#pragma unroll
        for (int j = 0; j < 4; j++)
#pragma unroll
            for (int q = 0; q < 4; q++) acc[i][j][q] = 0.f;

    auto issue = [&](int c, int buf) {
        int phase = c >> 4;
        int k0    = (c & 15) * 32;
        const __nv_bfloat16* Ap = (phase == 1) ? Alo : Ahi;
        const __nv_bfloat16* Bp = (phase == 2) ? Blo : Bhi;
        char* sA = smem + buf * 16384;
        char* sB = sA + 8192;
        cpasync16(sA + sRow0 * 64 + sSw0 * 16,
                  Ap + (size_t)(m0 + sRow0) * GK + k0 + sC16 * 8);
        cpasync16(sA + sRow1 * 64 + sSw1 * 16,
                  Ap + (size_t)(m0 + sRow1) * GK + k0 + sC16 * 8);
        int nA = n0 + sRow0, nB = n0 + sRow1;
        int cA = nA < N ? nA : N - 1, cB = nB < N ? nB : N - 1;
        cpasync16z(sB + sRow0 * 64 + sSw0 * 16,
                   Bp + (size_t)cA * GK + k0 + sC16 * 8, nA < N ? 16 : 0);
        cpasync16z(sB + sRow1 * 64 + sSw1 * 16,
                   Bp + (size_t)cB * GK + k0 + sC16 * 8, nB < N ? 16 : 0);
        cp_commit();
    };

    issue(0, 0);
    issue(1, 1);

    int buf = 0, nbuf = 2;
    for (int c = 0; c < NCH; c++) {
        if (c < NCH - 1) asm volatile("cp.async.wait_group 1;");
        else             asm volatile("cp.async.wait_group 0;");
        __syncthreads();

        uint32_t sAb = smemBase + buf * 16384;
        uint32_t sBb = sAb + 8192;

#pragma unroll
        for (int k16 = 0; k16 < 2; k16++) {
            int segA = k16 * 2 + aKhalf;
            int segB = k16 * 2 + (bG & 1);
            uint32_t af[4][4], bf[2][4];
#pragma unroll
            for (int mt = 0; mt < 4; mt++)
                ldmx4(af[mt], sAb + aRowOff[mt] + ((segA ^ aXor[mt]) << 4));
#pragma unroll
            for (int p = 0; p < 2; p++)
                ldmx4(bf[p], sBb + bRowOff[p] + ((segB ^ bXor[p]) << 4));
#pragma unroll
            for (int mt = 0; mt < 4; mt++)
#pragma unroll
                for (int nt = 0; nt < 4; nt++)
                    mma16816(acc[mt][nt], af[mt], &bf[nt >> 1][(nt & 1) * 2]);
        }
        if (c + 2 < NCH) issue(c + 2, nbuf);
        buf  = (buf  == 2) ? 0 : buf + 1;
        nbuf = (nbuf == 2) ? 0 : nbuf + 1;
    }

    // epilogue
    const int quad = lane >> 2, tq = lane & 3;
#pragma unroll
    for (int mt = 0; mt < 4; mt++) {
        int m = m0 + wm * 64 + mt * 16 + quad;
#pragma unroll
        for (int nt = 0; nt < 4; nt++) {
            int n = n0 + wn * 32 + nt * 8 + tq * 2;
            if (n < N) {
                float2 bv = *reinterpret_cast<const float2*>(&bias[n]);
                float2 o0, o1;
                o0.x = acc[mt][nt][0] + bv.x;
                o0.y = acc[mt][nt][1] + bv.y;
                o1.x = acc[mt][nt][2] + bv.x;
                o1.y = acc[mt][nt][3] + bv.y;
                *reinterpret_cast<float2*>(&C[(size_t)m * N + n]) = o0;
                *reinterpret_cast<float2*>(&C[(size_t)(m + 8) * N + n]) = o1;
            }
        }
    }
}

// ---------------------------------------------------------------------------
// flag-based grid barrier + persistent recurrence
// ---------------------------------------------------------------------------
__device__ __forceinline__ void cp_wait1() { asm volatile("cp.async.wait_group 1;"); }
__device__ __forceinline__ void cp_wait0() { asm volatile("cp.async.wait_group 0;"); }

// All blocks arrive at generation `target` (monotonic within launch; flags
// zeroed by k_reset before launch). No atomic contention: one flag per block,
// 128 poller threads each own one flag.
__device__ __forceinline__ void gbar(unsigned target) {
    __syncthreads();
    __threadfence();
    if (threadIdx.x == 0) {
        volatile unsigned* f = g_flags;
        f[blockIdx.x] = target;
    }
    if (threadIdx.x < NBLK) {
        volatile unsigned* f = g_flags;
        while (f[threadIdx.x] < target) {
#if __CUDA_ARCH__ >= 700
            __nanosleep(20);
#endif
        }
    }
    __syncthreads();
}

__global__ __launch_bounds__(NTHR, 1) void k_recur(const float* __restrict__ Uh,
                                                   const float* __restrict__ Uht) {
    extern __shared__ float smf[];
    float* sStage = smf;
    float* sUh    = sStage + 64 * STRIDE;
    float* sUht   = sUh + 4096;
    float* sPart  = sUht + 2048;
    float* sHold  = sPart + 2048;

    int tid   = threadIdx.x;
    int bid   = blockIdx.x;
    int colA0 = bid * 8;
    int colB0 = bid * 4;

    for (int i = tid; i < 512 * 2; i += NTHR) {
        int k = i >> 1, h4 = (i & 1) * 4;
        *reinterpret_cast<float4*>(&sUh[k * 8 + h4]) =
            *reinterpret_cast<const float4*>(&Uh[(size_t)k * (2 * HH) + colA0 + h4]);
    }
    for (int i = tid; i < 512; i += NTHR) {
        *reinterpret_cast<float4*>(&sUht[i * 4]) =
            *reinterpret_cast<const float4*>(&Uht[(size_t)i * HH + colB0]);
    }
    __syncthreads();

    const int kseg = tid >> 6;
    const int r2   = (tid >> 1) & 31;
    const int cg   = tid & 1;
    const int rowA = r2 * 2;
    const int rowB = tid & 63;

    unsigned gen = 0;

    for (int t = 0; t < TT; t++) {
        // ---- PHASE A ----
        {
            const float* src = g_hcur;
#pragma unroll
            for (int i = 0; i < 8; i++) {
                int idx = tid + i * NTHR;
                int row = idx >> 5, kq = (idx & 31) << 2;
                cpasync16(&sStage[row * STRIDE + kq], src + (size_t)row * HH + kq);
            }
            cp_commit();

            float acc[8];
#pragma unroll
            for (int i = 0; i < 8; i++) acc[i] = 0.f;

            for (int c = 0; c < 4; c++) {
                if (c < 3) {
#pragma unroll
                    for (int i = 0; i < 8; i++) {
                        int idx = tid + i * NTHR;
                        int row = idx >> 5, kq = (idx & 31) << 2;
                        int off = (c + 1) * 128 + kq;
                        cpasync16(&sStage[row * STRIDE + off],
                                  src + (size_t)row * HH + off);
                    }
                    cp_commit();
                    cp_wait1();
                } else {
                    cp_wait0();
                }
                __syncthreads();

                int kb = c * 128 + kseg * 32;
                const float* A0 = &sStage[rowA * STRIDE];
                const float* A1 = A0 + STRIDE;
#pragma unroll
                for (int kk = 0; kk < 32; kk++) {
                    int k = kb + kk;
                    float4 b = *reinterpret_cast<const float4*>(&sUh[k * 8 + cg * 4]);
                    float a0 = A0[k], a1 = A1[k];
                    acc[0] += a0 * b.x; acc[1] += a0 * b.y;
                    acc[2] += a0 * b.z; acc[3] += a0 * b.w;
                    acc[4] += a1 * b.x; acc[5] += a1 * b.y;
                    acc[6] += a1 * b.z; acc[7] += a1 * b.w;
                }
            }

            *reinterpret_cast<float4*>(&sPart[(kseg * 64 + rowA) * 8 + cg * 4]) =
                make_float4(acc[0], acc[1], acc[2], acc[3]);
            *reinterpret_cast<float4*>(&sPart[(kseg * 64 + rowA + 1) * 8 + cg * 4]) =
                make_float4(acc[4], acc[5], acc[6], acc[7]);
            __syncthreads();

#pragma unroll
            for (int j = 0; j < 2; j++) {
                int o   = tid + j * NTHR;
                int row = o >> 3, col = o & 7;
                float s = sPart[(0 * 64 + row) * 8 + col]
                        + sPart[(1 * 64 + row) * 8 + col]
                        + sPart[(2 * 64 + row) * 8 + col]
                        + sPart[(3 * 64 + row) * 8 + col];
                float pre = g_gx[((size_t)t * BB + row) * (3 * HH) + colA0 + col] + s;
                float sg = 1.f / (1.f + expf(-pre));
                if (colA0 < HH) {
                    int n = colA0 + col;
                    __stcg(&g_rh[row * HH + n], sg * sStage[row * STRIDE + n]);
                } else {
                    int n = colA0 + col - HH;
                    __stcg(&g_z[row * HH + n], sg);
                }
            }
        }
        gbar(++gen);

        {
            int row = tid >> 2, col = tid & 3;
            sHold[tid] = sStage[row * STRIDE + colB0 + col];
        }
        __syncthreads();

        // ---- PHASE B ----
        {
            const float* src = g_rh;
#pragma unroll
            for (int i = 0; i < 8; i++) {
                int idx = tid + i * NTHR;
                int row = idx >> 5, kq = (idx & 31) << 2;
                cpasync16(&sStage[row * STRIDE + kq], src + (size_t)row * HH + kq);
            }
            cp_commit();

            float acc[4] = {0.f, 0.f, 0.f, 0.f};

            for (int c = 0; c < 4; c++) {
                if (c < 3) {
#pragma unroll
                    for (int i = 0; i < 8; i++) {
                        int idx = tid + i * NTHR;
                        int row = idx >> 5, kq = (idx & 31) << 2;
                        int off = (c + 1) * 128 + kq;
                        cpasync16(&sStage[row * STRIDE + off],
                                  src + (size_t)row * HH + off);
                    }
                    cp_commit();
                    cp_wait1();
                } else {
                    cp_wait0();
                }
                __syncthreads();

                int kb = c * 128 + kseg * 32;
                const float* A0 = &sStage[rowB * STRIDE];
#pragma unroll
                for (int kk = 0; kk < 32; kk++) {
                    int k = kb + kk;
                    float4 b = *reinterpret_cast<const float4*>(&sUht[k * 4]);
                    float a = A0[k];
                    acc[0] += a * b.x; acc[1] += a * b.y;
                    acc[2] += a * b.z; acc[3] += a * b.w;
                }
            }

            *reinterpret_cast<float4*>(&sPart[(kseg * 64 + rowB) * 4]) =
                make_float4(acc[0], acc[1], acc[2], acc[3]);
            __syncthreads();

            {
                int row = tid >> 2, col = tid & 3;
                int n   = colB0 + col;
                float s = sPart[(0 * 64 + row) * 4 + col]
                        + sPart[(1 * 64 + row) * 4 + col]
                        + sPart[(2 * 64 + row) * 4 + col]
                        + sPart[(3 * 64 + row) * 4 + col];
                float pre  = g_gx[((size_t)t * BB + row) * (3 * HH) + 2 * HH + n] + s;
                float htil = tanhf(pre);
                float z  = __ldcg(&g_z[row * HH + n]);
                float hp = sHold[tid];
                float hn = (1.f - z) * hp + z * htil;
                __stcg(&g_hcur[row * HH + n], hn);
                g_hall[((size_t)t * BB + row) * HH + n] = hn;
            }
        }
        gbar(++gen);
    }
}

// ---------------------------------------------------------------------------
extern "C" void kernel_launch(void* const* d_in, const int* in_sizes, int n_in,
                              void* d_out, int out_size) {
    const int*   inputs    = (const int*)  d_in[0];
    const float* hidden    = (const float*)d_in[1];
    const float* emb_table = (const float*)d_in[2];
    const float* W_x       = (const float*)d_in[3];
    const float* U_h       = (const float*)d_in[4];
    const float* U_ht      = (const float*)d_in[5];
    const float* b_rzh     = (const float*)d_in[6];
    const float* fc_W      = (const float*)d_in[7];
    const float* fc_b      = (const float*)d_in[8];
    const float* dec_W     = (const float*)d_in[9];
    const float* dec_b     = (const float*)d_in[10];
    float* out = (float*)d_out;

    float *p_emb, *p_gx, *p_inp, *p_hall, *p_hcur, *p_wxT;
    cudaGetSymbolAddress((void**)&p_emb,  g_emb);
    cudaGetSymbolAddress((void**)&p_gx,   g_gx);
    cudaGetSymbolAddress((void**)&p_inp,  g_inp);
    cudaGetSymbolAddress((void**)&p_hall, g_hall);
    cudaGetSymbolAddress((void**)&p_hcur, g_hcur);
    cudaGetSymbolAddress((void**)&p_wxT,  g_wxT);

    __nv_bfloat16 *p_ahi, *p_alo, *p_wxh, *p_wxl, *p_fch, *p_fcl, *p_dech, *p_decl;
    cudaGetSymbolAddress((void**)&p_ahi,  g_ahi);
    cudaGetSymbolAddress((void**)&p_alo,  g_alo);
    cudaGetSymbolAddress((void**)&p_wxh,  g_wxh);
    cudaGetSymbolAddress((void**)&p_wxl,  g_wxl);
    cudaGetSymbolAddress((void**)&p_fch,  g_fch);
    cudaGetSymbolAddress((void**)&p_fcl,  g_fcl);
    cudaGetSymbolAddress((void**)&p_dech, g_dech);
    cudaGetSymbolAddress((void**)&p_decl, g_decl);

    const int RECUR_SMEM = (64 * STRIDE + 4096 + 2048 + 2048 + 256) * 4;
    cudaFuncSetAttribute(k_recur, cudaFuncAttributeMaxDynamicSharedMemorySize,
                         RECUR_SMEM);

    // 0) weight prep
    for (int l = 0; l < 2; l++)
        k_transpose<<<dim3(48, 16), dim3(32, 8)>>>(
            W_x + (size_t)l * HH * 3 * HH, p_wxT + (size_t)l * 3 * HH * HH,
            HH, 3 * HH);
    {
        int n4;
        n4 = 2 * 3 * HH * HH / 4;
        k_cvt<<<(n4 + 255) / 256, 256>>>(p_wxT, p_wxh, p_wxl, n4);
        n4 = 2 * HH * HH / 4;
        k_cvt<<<(n4 + 255) / 256, 256>>>(fc_W, p_fch, p_fcl, n4);
        n4 = VV * HH / 4;
        k_cvt<<<(n4 + 255) / 256, 256>>>(dec_W, p_dech, p_decl, n4);
    }

    // 1) embeddings + convert
    k_gather<<<MALL, 128>>>(inputs, emb_table);
    k_cvt<<<(MALL * HH / 4 + 255) / 256, 256>>>(p_emb, p_ahi, p_alo, MALL * HH / 4);

    // 2) gates_x for layer 0
    k_gemm_tc<<<dim3((3 * HH) / 128, MALL / 128), 256>>>(
        p_ahi, p_alo, p_wxh, p_wxl, b_rzh, p_gx, 3 * HH);

    long long need = (long long)TT * BB * VV + 2LL * BB * HH;

    for (int l = 0; l < 2; l++) {
        cudaMemcpyAsync(p_hcur, hidden + (size_t)l * BB * HH,
                        (size_t)BB * HH * sizeof(float), cudaMemcpyDeviceToDevice);

        k_reset<<<1, NBLK>>>();
        k_recur<<<NBLK, NTHR, RECUR_SMEM>>>(
            U_h  + (size_t)l * HH * 2 * HH,
            U_ht + (size_t)l * HH * HH);

        if ((long long)out_size >= need)
            cudaMemcpyAsync(out + (size_t)TT * BB * VV + (size_t)l * BB * HH, p_hcur,
                            (size_t)BB * HH * sizeof(float), cudaMemcpyDeviceToDevice);

        // fc: inp = h_all @ fc_W[l]^T + fc_b[l]
        k_cvt<<<(MALL * HH / 4 + 255) / 256, 256>>>(p_hall, p_ahi, p_alo,
                                                    MALL * HH / 4);
        k_gemm_tc<<<dim3(HH / 128, MALL / 128), 256>>>(
            p_ahi, p_alo,
            p_fch + (size_t)l * HH * HH, p_fcl + (size_t)l * HH * HH,
            fc_b + (size_t)l * HH, p_inp, HH);

        k_cvt<<<(MALL * HH / 4 + 255) / 256, 256>>>(p_inp, p_ahi, p_alo,
                                                    MALL * HH / 4);
        if (l == 0) {
            k_gemm_tc<<<dim3((3 * HH) / 128, MALL / 128), 256>>>(
                p_ahi, p_alo,
                p_wxh + (size_t)3 * HH * HH, p_wxl + (size_t)3 * HH * HH,
                b_rzh + 3 * HH, p_gx, 3 * HH);
        }
    }

    // decoder
    k_gemm_tc<<<dim3((VV + 127) / 128, MALL / 128), 256>>>(
        p_ahi, p_alo, p_dech, p_decl, dec_b, out, VV);
}

// round 9
// speedup vs baseline: 1.5150x; 1.5150x over previous
#include <cuda_runtime.h>
#include <cuda_bf16.h>
#include <math.h>
#include <stdint.h>

// ---------------------------------------------------------------------------
// GRU LM: T=128, B=64, E=H=512, V=10000, 2 layers.
// Round 9: round-7 baseline (2-stage GEMM, 1-poller barrier) +
//   (1) tree-arrive grid barrier (parallel group atomics, monotonic gens)
//   (2) bf16 hi/lo conversion fused into producers (no separate cvt passes
//       for activations; weights still converted once at prep).
// ---------------------------------------------------------------------------

#define TT   128
#define BB   64
#define HH   512
#define VV   10000
#define MALL (TT * BB)   // 8192
#define GK   512

#define NBLK   128
#define NTHR   256
#define STRIDE 516

// fp32 scratch
__device__ float g_gx  [MALL * 3 * HH];
__device__ float g_hcur[BB * HH];
__device__ float g_z   [BB * HH];
__device__ float g_rh  [BB * HH];
__device__ float g_wxT [2 * 3 * HH * HH];

// bf16 hi/lo activation planes (two streams, reused)
__device__ __nv_bfloat16 g_ahi [MALL * GK];   // P0: emb -> fc0 out -> fc1 out
__device__ __nv_bfloat16 g_alo [MALL * GK];
__device__ __nv_bfloat16 g_hhi [MALL * GK];   // PH: h_all planes
__device__ __nv_bfloat16 g_hlo [MALL * GK];

// bf16 weight planes
__device__ __nv_bfloat16 g_wxh [2 * 3 * HH * HH];
__device__ __nv_bfloat16 g_wxl [2 * 3 * HH * HH];
__device__ __nv_bfloat16 g_fch [2 * HH * HH];
__device__ __nv_bfloat16 g_fcl [2 * HH * HH];
__device__ __nv_bfloat16 g_dech[VV * HH];
__device__ __nv_bfloat16 g_decl[VV * HH];

// tree barrier state (zeroed by k_reset before each k_recur launch)
__device__ unsigned g_grpc[8 * 32];   // 8 group counters, 128B apart
__device__ unsigned g_rootc;
__device__ unsigned g_genw;

// ---------------------------------------------------------------------------
__global__ void k_reset() {
    int i = threadIdx.x;
    if (i < 8 * 32) g_grpc[i] = 0u;
    if (i == 0) { g_rootc = 0u; g_genw = 0u; }
}

// Embedding gather fused with hi/lo bf16 split.
__global__ void k_gather(const int* __restrict__ inp, const float* __restrict__ tbl,
                         __nv_bfloat16* __restrict__ hi,
                         __nv_bfloat16* __restrict__ lo) {
    int i   = blockIdx.x;
    int row = inp[i];
    const float4* src = reinterpret_cast<const float4*>(tbl + (size_t)row * HH);
    uint2* dh = reinterpret_cast<uint2*>(hi + (size_t)i * HH);
    uint2* dl = reinterpret_cast<uint2*>(lo + (size_t)i * HH);
    for (int j = threadIdx.x; j < HH / 4; j += blockDim.x) {
        float4 v = src[j];
        __nv_bfloat16 h0 = __float2bfloat16(v.x), h1 = __float2bfloat16(v.y),
                      h2 = __float2bfloat16(v.z), h3 = __float2bfloat16(v.w);
        __nv_bfloat16 l0 = __float2bfloat16(v.x - __bfloat162float(h0));
        __nv_bfloat16 l1 = __float2bfloat16(v.y - __bfloat162float(h1));
        __nv_bfloat16 l2 = __float2bfloat16(v.z - __bfloat162float(h2));
        __nv_bfloat16 l3 = __float2bfloat16(v.w - __bfloat162float(h3));
        uint2 hv, lv;
        hv.x = (uint32_t)__bfloat16_as_ushort(h0) | ((uint32_t)__bfloat16_as_ushort(h1) << 16);
        hv.y = (uint32_t)__bfloat16_as_ushort(h2) | ((uint32_t)__bfloat16_as_ushort(h3) << 16);
        lv.x = (uint32_t)__bfloat16_as_ushort(l0) | ((uint32_t)__bfloat16_as_ushort(l1) << 16);
        lv.y = (uint32_t)__bfloat16_as_ushort(l2) | ((uint32_t)__bfloat16_as_ushort(l3) << 16);
        dh[j] = hv;
        dl[j] = lv;
    }
}

// Transpose W[K][N] -> WT[N][K]
__global__ void k_transpose(const float* __restrict__ W, float* __restrict__ WT,
                            int K, int N) {
    __shared__ float tile[32][33];
    int k0 = blockIdx.y * 32, n0 = blockIdx.x * 32;
    int tx = threadIdx.x, ty = threadIdx.y;
#pragma unroll
    for (int i = 0; i < 32; i += 8)
        if (k0 + ty + i < K && n0 + tx < N)
            tile[ty + i][tx] = W[(size_t)(k0 + ty + i) * N + n0 + tx];
    __syncthreads();
#pragma unroll
    for (int i = 0; i < 32; i += 8)
        if (n0 + ty + i < N && k0 + tx < K)
            WT[(size_t)(n0 + ty + i) * K + k0 + tx] = tile[tx][ty + i];
}

// fp32 -> (hi, lo) bf16 planes (weights only, prep time).
__global__ void k_cvt(const float* __restrict__ src,
                      __nv_bfloat16* __restrict__ hi,
                      __nv_bfloat16* __restrict__ lo, int n4) {
    int i = blockIdx.x * blockDim.x + threadIdx.x;
    if (i >= n4) return;
    float4 v = reinterpret_cast<const float4*>(src)[i];
    __nv_bfloat16 h0 = __float2bfloat16(v.x), h1 = __float2bfloat16(v.y),
                  h2 = __float2bfloat16(v.z), h3 = __float2bfloat16(v.w);
    __nv_bfloat16 l0 = __float2bfloat16(v.x - __bfloat162float(h0));
    __nv_bfloat16 l1 = __float2bfloat16(v.y - __bfloat162float(h1));
    __nv_bfloat16 l2 = __float2bfloat16(v.z - __bfloat162float(h2));
    __nv_bfloat16 l3 = __float2bfloat16(v.w - __bfloat162float(h3));
    uint2 hv, lv;
    hv.x = (uint32_t)__bfloat16_as_ushort(h0) | ((uint32_t)__bfloat16_as_ushort(h1) << 16);
    hv.y = (uint32_t)__bfloat16_as_ushort(h2) | ((uint32_t)__bfloat16_as_ushort(h3) << 16);
    lv.x = (uint32_t)__bfloat16_as_ushort(l0) | ((uint32_t)__bfloat16_as_ushort(l1) << 16);
    lv.y = (uint32_t)__bfloat16_as_ushort(l2) | ((uint32_t)__bfloat16_as_ushort(l3) << 16);
    reinterpret_cast<uint2*>(hi)[i] = hv;
    reinterpret_cast<uint2*>(lo)[i] = lv;
}

// ---------------------------------------------------------------------------
// mma.sync helpers
// ---------------------------------------------------------------------------
__device__ __forceinline__ void cpasync16(void* dst_smem, const void* src) {
    uint32_t d = (uint32_t)__cvta_generic_to_shared(dst_smem);
    asm volatile("cp.async.cg.shared.global [%0], [%1], 16;" :: "r"(d), "l"(src));
}
__device__ __forceinline__ void cpasync16z(void* dst_smem, const void* src, int sz) {
    uint32_t d = (uint32_t)__cvta_generic_to_shared(dst_smem);
    asm volatile("cp.async.cg.shared.global [%0], [%1], 16, %2;"
                 :: "r"(d), "l"(src), "r"(sz));
}
__device__ __forceinline__ void cp_commit() { asm volatile("cp.async.commit_group;"); }

__device__ __forceinline__ void ldmx4(uint32_t* r, uint32_t addr) {
    asm volatile("ldmatrix.sync.aligned.m8n8.x4.shared.b16 {%0,%1,%2,%3}, [%4];"
                 : "=r"(r[0]), "=r"(r[1]), "=r"(r[2]), "=r"(r[3]) : "r"(addr));
}
__device__ __forceinline__ void mma16816(float* d, const uint32_t* a, const uint32_t* b) {
    asm volatile(
        "mma.sync.aligned.m16n8k16.row.col.f32.bf16.bf16.f32 "
        "{%0,%1,%2,%3}, {%4,%5,%6,%7}, {%8,%9}, {%0,%1,%2,%3};"
        : "+f"(d[0]), "+f"(d[1]), "+f"(d[2]), "+f"(d[3])
        : "r"(a[0]), "r"(a[1]), "r"(a[2]), "r"(a[3]), "r"(b[0]), "r"(b[1]));
}

__device__ __forceinline__ uint32_t pack_hl_hi(float x, float y) {
    __nv_bfloat16 hx = __float2bfloat16(x), hy = __float2bfloat16(y);
    return (uint32_t)__bfloat16_as_ushort(hx) | ((uint32_t)__bfloat16_as_ushort(hy) << 16);
}
__device__ __forceinline__ uint32_t pack_hl_lo(float x, float y) {
    __nv_bfloat16 hx = __float2bfloat16(x), hy = __float2bfloat16(y);
    __nv_bfloat16 lx = __float2bfloat16(x - __bfloat162float(hx));
    __nv_bfloat16 ly = __float2bfloat16(y - __bfloat162float(hy));
    return (uint32_t)__bfloat16_as_ushort(lx) | ((uint32_t)__bfloat16_as_ushort(ly) << 16);
}

// ---------------------------------------------------------------------------
// Tensor-core GEMM (round-7 2-stage, unchanged mainloop).
// OUT=0: C fp32.  OUT=1: Chi/Clo bf16 planes (bias included before split).
// ---------------------------------------------------------------------------
#define NCH 48   // 3 phases * 512/32

template <int OUT>
__global__ __launch_bounds__(256)
void k_gemm_tc(const __nv_bfloat16* __restrict__ Ahi,
               const __nv_bfloat16* __restrict__ Alo,
               const __nv_bfloat16* __restrict__ Bhi,
               const __nv_bfloat16* __restrict__ Blo,
               const float* __restrict__ bias, float* __restrict__ C,
               __nv_bfloat16* __restrict__ Chi, __nv_bfloat16* __restrict__ Clo,
               int N) {
    __shared__ __align__(16) char smem[2 * 16384];

    const int tid  = threadIdx.x;
    const int lane = tid & 31;
    const int wid  = tid >> 5;
    const int wm   = wid >> 2;
    const int wn   = wid & 3;
    const int m0   = blockIdx.y * 128;
    const int n0   = blockIdx.x * 128;

    const int sRow0 = tid >> 2;
    const int sC16  = tid & 3;
    const int sSw0  = sC16 ^ ((sRow0 >> 1) & 3);
    const int sRow1 = sRow0 + 64;
    const int sSw1  = sC16 ^ ((sRow1 >> 1) & 3);

    const int aRow16 = lane & 15;
    const int aKhalf = lane >> 4;
    const int bL8 = lane & 7, bG = lane >> 3;

    int  aRowOff[4], aXor[4];
#pragma unroll
    for (int mt = 0; mt < 4; mt++) {
        int r = wm * 64 + mt * 16 + aRow16;
        aRowOff[mt] = r * 64;
        aXor[mt]    = (r >> 1) & 3;
    }
    int  bRowOff[2], bXor[2];
#pragma unroll
    for (int p = 0; p < 2; p++) {
        int r = wn * 32 + p * 16 + ((bG >> 1) << 3) + bL8;
        bRowOff[p] = r * 64;
        bXor[p]    = (r >> 1) & 3;
    }
    const uint32_t smemBase = (uint32_t)__cvta_generic_to_shared(smem);

    float acc[4][4][4];
#pragma unroll
    for (int i = 0; i < 4; i++)
#pragma unroll
        for (int j = 0; j < 4; j++)
#pragma unroll
            for (int q = 0; q < 4; q++) acc[i][j][q] = 0.f;

    auto issue = [&](int c) {
        int phase = c >> 4;
        int k0    = (c & 15) * 32;
        const __nv_bfloat16* Ap = (phase == 1) ? Alo : Ahi;
        const __nv_bfloat16* Bp = (phase == 2) ? Blo : Bhi;
        char* sA = smem + (c & 1) * 16384;
        char* sB = sA + 8192;
        cpasync16(sA + sRow0 * 64 + sSw0 * 16,
                  Ap + (size_t)(m0 + sRow0) * GK + k0 + sC16 * 8);
        cpasync16(sA + sRow1 * 64 + sSw1 * 16,
                  Ap + (size_t)(m0 + sRow1) * GK + k0 + sC16 * 8);
        int nA = n0 + sRow0, nB = n0 + sRow1;
        int cA = nA < N ? nA : N - 1, cB = nB < N ? nB : N - 1;
        cpasync16z(sB + sRow0 * 64 + sSw0 * 16,
                   Bp + (size_t)cA * GK + k0 + sC16 * 8, nA < N ? 16 : 0);
        cpasync16z(sB + sRow1 * 64 + sSw1 * 16,
                   Bp + (size_t)cB * GK + k0 + sC16 * 8, nB < N ? 16 : 0);
        cp_commit();
    };

    issue(0);
    issue(1);

    for (int c = 0; c < NCH; c++) {
        if (c < NCH - 1) asm volatile("cp.async.wait_group 1;");
        else             asm volatile("cp.async.wait_group 0;");
        __syncthreads();

        uint32_t sAb = smemBase + (c & 1) * 16384;
        uint32_t sBb = sAb + 8192;

#pragma unroll
        for (int k16 = 0; k16 < 2; k16++) {
            int segA = k16 * 2 + aKhalf;
            int segB = k16 * 2 + (bG & 1);
            uint32_t af[4][4], bf[2][4];
#pragma unroll
            for (int mt = 0; mt < 4; mt++)
                ldmx4(af[mt], sAb + aRowOff[mt] + ((segA ^ aXor[mt]) << 4));
#pragma unroll
            for (int p = 0; p < 2; p++)
                ldmx4(bf[p], sBb + bRowOff[p] + ((segB ^ bXor[p]) << 4));
#pragma unroll
            for (int mt = 0; mt < 4; mt++)
#pragma unroll
                for (int nt = 0; nt < 4; nt++)
                    mma16816(acc[mt][nt], af[mt], &bf[nt >> 1][(nt & 1) * 2]);
        }
        __syncthreads();
        if (c + 2 < NCH) issue(c + 2);
    }

    // epilogue
    const int quad = lane >> 2, tq = lane & 3;
#pragma unroll
    for (int mt = 0; mt < 4; mt++) {
        int m = m0 + wm * 64 + mt * 16 + quad;
#pragma unroll
        for (int nt = 0; nt < 4; nt++) {
            int n = n0 + wn * 32 + nt * 8 + tq * 2;
            if (n < N) {
                float2 bv = *reinterpret_cast<const float2*>(&bias[n]);
                float o0x = acc[mt][nt][0] + bv.x;
                float o0y = acc[mt][nt][1] + bv.y;
                float o1x = acc[mt][nt][2] + bv.x;
                float o1y = acc[mt][nt][3] + bv.y;
                if (OUT == 0) {
                    *reinterpret_cast<float2*>(&C[(size_t)m * N + n]) =
                        make_float2(o0x, o0y);
                    *reinterpret_cast<float2*>(&C[(size_t)(m + 8) * N + n]) =
                        make_float2(o1x, o1y);
                } else {
                    *reinterpret_cast<uint32_t*>(&Chi[(size_t)m * N + n]) =
                        pack_hl_hi(o0x, o0y);
                    *reinterpret_cast<uint32_t*>(&Clo[(size_t)m * N + n]) =
                        pack_hl_lo(o0x, o0y);
                    *reinterpret_cast<uint32_t*>(&Chi[(size_t)(m + 8) * N + n]) =
                        pack_hl_hi(o1x, o1y);
                    *reinterpret_cast<uint32_t*>(&Clo[(size_t)(m + 8) * N + n]) =
                        pack_hl_lo(o1x, o1y);
                }
            }
        }
    }
}

// ---------------------------------------------------------------------------
// Tree-arrive grid barrier: 1 poller per block. Arrive: 16-way group atomics
// (8 padded counters, parallel across LTS) then 8-way root. Monotonic
// thresholds (16*gen, 8*gen) -> no counter resets between barriers.
// ---------------------------------------------------------------------------
__device__ __forceinline__ void cp_wait1() { asm volatile("cp.async.wait_group 1;"); }
__device__ __forceinline__ void cp_wait0() { asm volatile("cp.async.wait_group 0;"); }

__device__ __forceinline__ void gbar(unsigned gen) {
    __syncthreads();
    if (threadIdx.x == 0) {
        __threadfence();
        unsigned g = blockIdx.x >> 4;
        unsigned v = atomicAdd(&g_grpc[g * 32], 1u) + 1u;
        if (v == 16u * gen) {
            unsigned r = atomicAdd(&g_rootc, 1u) + 1u;
            if (r == 8u * gen) {
                __threadfence();
                atomicExch(&g_genw, gen);
            }
        }
        unsigned cur;
        do {
            asm volatile("ld.global.cg.u32 %0, [%1];" : "=r"(cur) : "l"(&g_genw));
            if (cur >= gen) break;
#if __CUDA_ARCH__ >= 700
            __nanosleep(20);
#endif
        } while (true);
        __threadfence();
    }
    __syncthreads();
}

// ---------------------------------------------------------------------------
// Persistent recurrence: phase B writes h_all directly as bf16 hi/lo planes.
// ---------------------------------------------------------------------------
__global__ __launch_bounds__(NTHR, 1) void k_recur(const float* __restrict__ Uh,
                                                   const float* __restrict__ Uht) {
    extern __shared__ float smf[];
    float* sStage = smf;
    float* sUh    = sStage + 64 * STRIDE;
    float* sUht   = sUh + 4096;
    float* sPart  = sUht + 2048;
    float* sHold  = sPart + 2048;

    int tid   = threadIdx.x;
    int bid   = blockIdx.x;
    int colA0 = bid * 8;
    int colB0 = bid * 4;

    for (int i = tid; i < 512 * 2; i += NTHR) {
        int k = i >> 1, h4 = (i & 1) * 4;
        *reinterpret_cast<float4*>(&sUh[k * 8 + h4]) =
            *reinterpret_cast<const float4*>(&Uh[(size_t)k * (2 * HH) + colA0 + h4]);
    }
    for (int i = tid; i < 512; i += NTHR) {
        *reinterpret_cast<float4*>(&sUht[i * 4]) =
            *reinterpret_cast<const float4*>(&Uht[(size_t)i * HH + colB0]);
    }
    __syncthreads();

    const int kseg = tid >> 6;
    const int r2   = (tid >> 1) & 31;
    const int cg   = tid & 1;
    const int rowA = r2 * 2;
    const int rowB = tid & 63;

    unsigned gen = 0;

    for (int t = 0; t < TT; t++) {
        // ---- PHASE A ----
        {
            const float* src = g_hcur;
#pragma unroll
            for (int i = 0; i < 8; i++) {
                int idx = tid + i * NTHR;
                int row = idx >> 5, kq = (idx & 31) << 2;
                cpasync16(&sStage[row * STRIDE + kq], src + (size_t)row * HH + kq);
            }
            cp_commit();

            float acc[8];
#pragma unroll
            for (int i = 0; i < 8; i++) acc[i] = 0.f;

            for (int c = 0; c < 4; c++) {
                if (c < 3) {
#pragma unroll
                    for (int i = 0; i < 8; i++) {
                        int idx = tid + i * NTHR;
                        int row = idx >> 5, kq = (idx & 31) << 2;
                        int off = (c + 1) * 128 + kq;
                        cpasync16(&sStage[row * STRIDE + off],
                                  src + (size_t)row * HH + off);
                    }
                    cp_commit();
                    cp_wait1();
                } else {
                    cp_wait0();
                }
                __syncthreads();

                int kb = c * 128 + kseg * 32;
                const float* A0 = &sStage[rowA * STRIDE];
                const float* A1 = A0 + STRIDE;
#pragma unroll
                for (int kk = 0; kk < 32; kk++) {
                    int k = kb + kk;
                    float4 b = *reinterpret_cast<const float4*>(&sUh[k * 8 + cg * 4]);
                    float a0 = A0[k], a1 = A1[k];
                    acc[0] += a0 * b.x; acc[1] += a0 * b.y;
                    acc[2] += a0 * b.z; acc[3] += a0 * b.w;
                    acc[4] += a1 * b.x; acc[5] += a1 * b.y;
                    acc[6] += a1 * b.z; acc[7] += a1 * b.w;
                }
            }

            *reinterpret_cast<float4*>(&sPart[(kseg * 64 + rowA) * 8 + cg * 4]) =
                make_float4(acc[0], acc[1], acc[2], acc[3]);
            *reinterpret_cast<float4*>(&sPart[(kseg * 64 + rowA + 1) * 8 + cg * 4]) =
                make_float4(acc[4], acc[5], acc[6], acc[7]);
            __syncthreads();

#pragma unroll
            for (int j = 0; j < 2; j++) {
                int o   = tid + j * NTHR;
                int row = o >> 3, col = o & 7;
                float s = sPart[(0 * 64 + row) * 8 + col]
                        + sPart[(1 * 64 + row) * 8 + col]
                        + sPart[(2 * 64 + row) * 8 + col]
                        + sPart[(3 * 64 + row) * 8 + col];
                float pre = g_gx[((size_t)t * BB + row) * (3 * HH) + colA0 + col] + s;
                float sg = 1.f / (1.f + expf(-pre));
                if (colA0 < HH) {
                    int n = colA0 + col;
                    __stcg(&g_rh[row * HH + n], sg * sStage[row * STRIDE + n]);
                } else {
                    int n = colA0 + col - HH;
                    __stcg(&g_z[row * HH + n], sg);
                }
            }
        }
        gbar(++gen);

        {
            int row = tid >> 2, col = tid & 3;
            sHold[tid] = sStage[row * STRIDE + colB0 + col];
        }
        __syncthreads();

        // ---- PHASE B ----
        {
            const float* src = g_rh;
#pragma unroll
            for (int i = 0; i < 8; i++) {
                int idx = tid + i * NTHR;
                int row = idx >> 5, kq = (idx & 31) << 2;
                cpasync16(&sStage[row * STRIDE + kq], src + (size_t)row * HH + kq);
            }
            cp_commit();

            float acc[4] = {0.f, 0.f, 0.f, 0.f};

            for (int c = 0; c < 4; c++) {
                if (c < 3) {
#pragma unroll
                    for (int i = 0; i < 8; i++) {
                        int idx = tid + i * NTHR;
                        int row = idx >> 5, kq = (idx & 31) << 2;
                        int off = (c + 1) * 128 + kq;
                        cpasync16(&sStage[row * STRIDE + off],
                                  src + (size_t)row * HH + off);
                    }
                    cp_commit();
                    cp_wait1();
                } else {
                    cp_wait0();
                }
                __syncthreads();

                int kb = c * 128 + kseg * 32;
                const float* A0 = &sStage[rowB * STRIDE];
#pragma unroll
                for (int kk = 0; kk < 32; kk++) {
                    int k = kb + kk;
                    float4 b = *reinterpret_cast<const float4*>(&sUht[k * 4]);
                    float a = A0[k];
                    acc[0] += a * b.x; acc[1] += a * b.y;
                    acc[2] += a * b.z; acc[3] += a * b.w;
                }
            }

            *reinterpret_cast<float4*>(&sPart[(kseg * 64 + rowB) * 4]) =
                make_float4(acc[0], acc[1], acc[2], acc[3]);
            __syncthreads();

            {
                int row = tid >> 2, col = tid & 3;
                int n   = colB0 + col;
                float s = sPart[(0 * 64 + row) * 4 + col]
                        + sPart[(1 * 64 + row) * 4 + col]
                        + sPart[(2 * 64 + row) * 4 + col]
                        + sPart[(3 * 64 + row) * 4 + col];
                float pre  = g_gx[((size_t)t * BB + row) * (3 * HH) + 2 * HH + n] + s;
                float htil = tanhf(pre);
                float z  = __ldcg(&g_z[row * HH + n]);
                float hp = sHold[tid];
                float hn = (1.f - z) * hp + z * htil;
                __stcg(&g_hcur[row * HH + n], hn);
                // fused hi/lo write of h_all
                __nv_bfloat16 hh = __float2bfloat16(hn);
                __nv_bfloat16 hl = __float2bfloat16(hn - __bfloat162float(hh));
                size_t o = ((size_t)t * BB + row) * HH + n;
                g_hhi[o] = hh;
                g_hlo[o] = hl;
            }
        }
        gbar(++gen);
    }
}

// ---------------------------------------------------------------------------
extern "C" void kernel_launch(void* const* d_in, const int* in_sizes, int n_in,
                              void* d_out, int out_size) {
    const int*   inputs    = (const int*)  d_in[0];
    const float* hidden    = (const float*)d_in[1];
    const float* emb_table = (const float*)d_in[2];
    const float* W_x       = (const float*)d_in[3];
    const float* U_h       = (const float*)d_in[4];
    const float* U_ht      = (const float*)d_in[5];
    const float* b_rzh     = (const float*)d_in[6];
    const float* fc_W      = (const float*)d_in[7];
    const float* fc_b      = (const float*)d_in[8];
    const float* dec_W     = (const float*)d_in[9];
    const float* dec_b     = (const float*)d_in[10];
    float* out = (float*)d_out;

    float *p_gx, *p_hcur, *p_wxT;
    cudaGetSymbolAddress((void**)&p_gx,   g_gx);
    cudaGetSymbolAddress((void**)&p_hcur, g_hcur);
    cudaGetSymbolAddress((void**)&p_wxT,  g_wxT);

    __nv_bfloat16 *p_ahi, *p_alo, *p_hhi, *p_hlo;
    __nv_bfloat16 *p_wxh, *p_wxl, *p_fch, *p_fcl, *p_dech, *p_decl;
    cudaGetSymbolAddress((void**)&p_ahi,  g_ahi);
    cudaGetSymbolAddress((void**)&p_alo,  g_alo);
    cudaGetSymbolAddress((void**)&p_hhi,  g_hhi);
    cudaGetSymbolAddress((void**)&p_hlo,  g_hlo);
    cudaGetSymbolAddress((void**)&p_wxh,  g_wxh);
    cudaGetSymbolAddress((void**)&p_wxl,  g_wxl);
    cudaGetSymbolAddress((void**)&p_fch,  g_fch);
    cudaGetSymbolAddress((void**)&p_fcl,  g_fcl);
    cudaGetSymbolAddress((void**)&p_dech, g_dech);
    cudaGetSymbolAddress((void**)&p_decl, g_decl);

    const int RECUR_SMEM = (64 * STRIDE + 4096 + 2048 + 2048 + 256) * 4;
    cudaFuncSetAttribute(k_recur, cudaFuncAttributeMaxDynamicSharedMemorySize,
                         RECUR_SMEM);

    // 0) weight prep
    for (int l = 0; l < 2; l++)
        k_transpose<<<dim3(48, 16), dim3(32, 8)>>>(
            W_x + (size_t)l * HH * 3 * HH, p_wxT + (size_t)l * 3 * HH * HH,
            HH, 3 * HH);
    {
        int n4;
        n4 = 2 * 3 * HH * HH / 4;
        k_cvt<<<(n4 + 255) / 256, 256>>>(p_wxT, p_wxh, p_wxl, n4);
        n4 = 2 * HH * HH / 4;
        k_cvt<<<(n4 + 255) / 256, 256>>>(fc_W, p_fch, p_fcl, n4);
        n4 = VV * HH / 4;
        k_cvt<<<(n4 + 255) / 256, 256>>>(dec_W, p_dech, p_decl, n4);
    }

    // 1) embeddings -> P0 planes (fused cvt)
    k_gather<<<MALL, 128>>>(inputs, emb_table, p_ahi, p_alo);

    // 2) gates_x for layer 0 (fp32 out)
    k_gemm_tc<0><<<dim3((3 * HH) / 128, MALL / 128), 256>>>(
        p_ahi, p_alo, p_wxh, p_wxl, b_rzh, p_gx, nullptr, nullptr, 3 * HH);

    long long need = (long long)TT * BB * VV + 2LL * BB * HH;

    for (int l = 0; l < 2; l++) {
        cudaMemcpyAsync(p_hcur, hidden + (size_t)l * BB * HH,
                        (size_t)BB * HH * sizeof(float), cudaMemcpyDeviceToDevice);

        k_reset<<<1, 256>>>();
        k_recur<<<NBLK, NTHR, RECUR_SMEM>>>(
            U_h  + (size_t)l * HH * 2 * HH,
            U_ht + (size_t)l * HH * HH);

        if ((long long)out_size >= need)
            cudaMemcpyAsync(out + (size_t)TT * BB * VV + (size_t)l * BB * HH, p_hcur,
                            (size_t)BB * HH * sizeof(float), cudaMemcpyDeviceToDevice);

        // fc: PH planes -> P0 planes (bias included, bf16 hi/lo out)
        k_gemm_tc<1><<<dim3(HH / 128, MALL / 128), 256>>>(
            p_hhi, p_hlo,
            p_fch + (size_t)l * HH * HH, p_fcl + (size_t)l * HH * HH,
            fc_b + (size_t)l * HH, nullptr, p_ahi, p_alo, HH);

        if (l == 0) {
            k_gemm_tc<0><<<dim3((3 * HH) / 128, MALL / 128), 256>>>(
                p_ahi, p_alo,
                p_wxh + (size_t)3 * HH * HH, p_wxl + (size_t)3 * HH * HH,
                b_rzh + 3 * HH, p_gx, nullptr, nullptr, 3 * HH);
        }
    }

    // decoder (fp32 out)
    k_gemm_tc<0><<<dim3((VV + 127) / 128, MALL / 128), 256>>>(
        p_ahi, p_alo, p_dech, p_decl, dec_b, out, nullptr, nullptr, VV);
}